// round 1
// baseline (speedup 1.0000x reference)
#include <cuda_runtime.h>
#include <cuda_bf16.h>
#include <cstdint>

// ---------------------------------------------------------------------------
// GradientLayerPoisson: 2nd-order forward jet through tanh MLP 2->256->256->256->1
// out = [u(B) | du/dx0(B) | d2u/dx0^2(B)]
//
// Fully fused: one block processes 32 samples end-to-end, activations jet
// (h, h', h'') ping-pongs between two SMEM buffers. GEMMs use packed
// fp32x2 FFMA (fma.rn.f32x2) for 2x fp32 throughput.
// ---------------------------------------------------------------------------

#define HID 256
#define TS 32            // samples per block
#define HPAD 257         // row pad: stride 257 -> conflict-free (s*257+k)%32
#define HBUF (3*TS*HPAD) // one jet buffer (floats)

#define HIDX(st, s, u) (((st)*TS + (s))*HPAD + (u))

__device__ __forceinline__ unsigned long long pack2(float x) {
    unsigned long long r;
    asm("mov.b64 %0, {%1, %1};" : "=l"(r) : "f"(x));
    return r;
}

__device__ __forceinline__ unsigned long long ffma2(unsigned long long a,
                                                    unsigned long long b,
                                                    unsigned long long c) {
    unsigned long long d;
    asm("fma.rn.f32x2 %0, %1, %2, %3;" : "=l"(d) : "l"(a), "l"(b), "l"(c));
    return d;
}

__device__ __forceinline__ void unpack2(unsigned long long v, float& lo, float& hi) {
    asm("mov.b64 {%0, %1}, %2;" : "=f"(lo), "=f"(hi) : "l"(v));
}

// tanh + sech^2 via EX2 + approx-rcp + 1 Newton step.
// tanh(x) = 1 - 2/(1+e^{2x});  1 - tanh^2 = 4 r (1 - r),  r = 1/(1+e^{2x})
__device__ __forceinline__ void tanh_d(float x, float& a, float& s2) {
    x = fminf(fmaxf(x, -15.f), 15.f);
    float t = exp2f(x * 2.8853900817779268f);  // e^{2x}
    float d = 1.f + t;
    float r;
    asm("rcp.approx.ftz.f32 %0, %1;" : "=f"(r) : "f"(d));
    r = r * (2.f - d * r);     // Newton refine -> ~fp32 accurate
    a  = 1.f - 2.f * r;
    s2 = 4.f * r * (1.f - r);
}

// GEMM: dst[st][s][:] = src[st][s][:] @ W   (3 jet streams, shared W)
// 256 threads: lane s = t&31 (sample), ug = t>>5 (8 units of the 64-unit tile)
__device__ __forceinline__ void jet_gemm(const float* __restrict__ Wg,
                                         const float* __restrict__ src,
                                         float* __restrict__ dst,
                                         float* __restrict__ WS, int t) {
    const int s  = t & 31;
    const int ug = t >> 5;
    #pragma unroll 1
    for (int tile = 0; tile < 4; ++tile) {
        const int u0 = tile * 64;
        unsigned long long acc[12];
        #pragma unroll
        for (int i = 0; i < 12; ++i) acc[i] = 0ull;

        #pragma unroll 1
        for (int kk = 0; kk < HID; kk += 64) {
            __syncthreads();  // protect WS reuse
            // stage W[kk..kk+64)[u0..u0+64) -> WS[64][64]
            #pragma unroll
            for (int r = 0; r < 4; ++r) {
                int f  = t + 256 * r;       // float4 index, 1024 total
                int kr = f >> 4;
                int c4 = f & 15;
                ((float4*)WS)[f] =
                    *(const float4*)(&Wg[(kk + kr) * HID + u0 + c4 * 4]);
            }
            __syncthreads();

            #pragma unroll 8
            for (int k = 0; k < 64; ++k) {
                float h0 = src[HIDX(0, s, kk + k)];
                float h1 = src[HIDX(1, s, kk + k)];
                float h2 = src[HIDX(2, s, kk + k)];
                unsigned long long hp0 = pack2(h0);
                unsigned long long hp1 = pack2(h1);
                unsigned long long hp2 = pack2(h2);
                const ulonglong2* wp =
                    (const ulonglong2*)(WS + k * 64 + ug * 8);
                ulonglong2 wa = wp[0];
                ulonglong2 wb = wp[1];
                acc[0]  = ffma2(hp0, wa.x, acc[0]);
                acc[1]  = ffma2(hp0, wa.y, acc[1]);
                acc[2]  = ffma2(hp0, wb.x, acc[2]);
                acc[3]  = ffma2(hp0, wb.y, acc[3]);
                acc[4]  = ffma2(hp1, wa.x, acc[4]);
                acc[5]  = ffma2(hp1, wa.y, acc[5]);
                acc[6]  = ffma2(hp1, wb.x, acc[6]);
                acc[7]  = ffma2(hp1, wb.y, acc[7]);
                acc[8]  = ffma2(hp2, wa.x, acc[8]);
                acc[9]  = ffma2(hp2, wa.y, acc[9]);
                acc[10] = ffma2(hp2, wb.x, acc[10]);
                acc[11] = ffma2(hp2, wb.y, acc[11]);
            }
        }
        // store raw z (bias added in tanh phase)
        #pragma unroll
        for (int st = 0; st < 3; ++st)
            #pragma unroll
            for (int p = 0; p < 4; ++p) {
                float lo, hi;
                unpack2(acc[st * 4 + p], lo, hi);
                int u = u0 + ug * 8 + 2 * p;
                dst[HIDX(st, s, u)]     = lo;
                dst[HIDX(st, s, u + 1)] = hi;
            }
    }
}

// elementwise tanh-jet (in place), thread t owns unit j=t for all samples
__device__ __forceinline__ void tanh_phase(float* __restrict__ Z,
                                           const float* __restrict__ bias,
                                           int t) {
    float bb = bias[t];
    #pragma unroll 4
    for (int i = 0; i < TS; ++i) {
        float z  = Z[HIDX(0, i, t)] + bb;
        float z1 = Z[HIDX(1, i, t)];
        float z2 = Z[HIDX(2, i, t)];
        float a, s2;
        tanh_d(z, a, s2);
        float a1 = s2 * z1;
        float a2 = s2 * z2 - 2.f * a * a1 * z1;
        Z[HIDX(0, i, t)] = a;
        Z[HIDX(1, i, t)] = a1;
        Z[HIDX(2, i, t)] = a2;
    }
}

extern "C" __global__ void __launch_bounds__(256, 1)
pinn_jet_kernel(const float* __restrict__ x,
                const float* __restrict__ W1, const float* __restrict__ b1,
                const float* __restrict__ W2, const float* __restrict__ b2,
                const float* __restrict__ W3, const float* __restrict__ b3,
                const float* __restrict__ W4, const float* __restrict__ b4,
                float* __restrict__ out, int B) {
    extern __shared__ float smem[];
    float* HA = smem;
    float* HB = HA + HBUF;
    float* WS = HB + HBUF;  // 64*64 floats, also reused to stage x

    const int t  = threadIdx.x;
    const int bs = blockIdx.x * TS;  // first sample of this block

    // ---- layer 1: x(2) -> HID, jet seeds: z' = W1[0,:], z'' = 0 ----
    if (t < TS) {
        float2 xv = ((const float2*)x)[bs + t];
        WS[2 * t]     = xv.x;
        WS[2 * t + 1] = xv.y;
    }
    __syncthreads();
    {
        const int j = t;  // unit
        float c0 = W1[j];
        float c1 = W1[HID + j];
        float bb = b1[j];
        #pragma unroll 4
        for (int i = 0; i < TS; ++i) {
            float z = fmaf(WS[2 * i], c0, fmaf(WS[2 * i + 1], c1, bb));
            float a, s2;
            tanh_d(z, a, s2);
            float a1 = s2 * c0;                 // (1-a^2) * z'   (z' = c0)
            float a2 = -2.f * a * a1 * c0;      // z'' = 0
            HA[HIDX(0, i, j)] = a;
            HA[HIDX(1, i, j)] = a1;
            HA[HIDX(2, i, j)] = a2;
        }
    }
    __syncthreads();

    // ---- layer 2 ----
    jet_gemm(W2, HA, HB, WS, t);
    __syncthreads();
    tanh_phase(HB, b2, t);
    __syncthreads();

    // ---- layer 3 ----
    jet_gemm(W3, HB, HA, WS, t);
    __syncthreads();
    tanh_phase(HA, b3, t);
    __syncthreads();

    // ---- output layer: dot with W4 (HID x 1) per jet stream ----
    if (t < 96) {
        const int st = t >> 5;
        const int s  = t & 31;
        float sum = 0.f;
        #pragma unroll 8
        for (int j = 0; j < HID; ++j)
            sum = fmaf(HA[HIDX(st, s, j)], W4[j], sum);
        if (st == 0) sum += b4[0];
        out[st * B + bs + s] = sum;
    }
}

extern "C" void kernel_launch(void* const* d_in, const int* in_sizes, int n_in,
                              void* d_out, int out_size) {
    const float* x  = (const float*)d_in[0];
    const float* W1 = (const float*)d_in[1];
    const float* b1 = (const float*)d_in[2];
    const float* W2 = (const float*)d_in[3];
    const float* b2 = (const float*)d_in[4];
    const float* W3 = (const float*)d_in[5];
    const float* b3 = (const float*)d_in[6];
    const float* W4 = (const float*)d_in[7];
    const float* b4 = (const float*)d_in[8];
    float* out = (float*)d_out;

    const int B = in_sizes[0] / 2;  // x is (B, 2)
    const size_t smem = (size_t)(2 * HBUF + 64 * 64) * sizeof(float);

    cudaFuncSetAttribute(pinn_jet_kernel,
                         cudaFuncAttributeMaxDynamicSharedMemorySize,
                         (int)smem);

    pinn_jet_kernel<<<B / TS, 256, smem>>>(x, W1, b1, W2, b2, W3, b3, W4, b4,
                                           out, B);
}